// round 1
// baseline (speedup 1.0000x reference)
#include <cuda_runtime.h>
#include <math_constants.h>

#define Bdim 512
#define Tdim 256
#define Fdim 1024
#define ATC  16   // T-rows per streamed chunk in attention kernel

// Scratch (no allocations allowed): 2 MB each
__device__ float g_query[Bdim * Fdim];
__device__ float g_qk[Bdim * Fdim];
__device__ float g_ctxin[Bdim * Fdim];

// ---------------------------------------------------------------------------
// Tiled fp32 GEMM: C[M,N] = A[M,K] * op(B) (+ bias over N)
//   BNT = true : B is [N,K] row-major (dot of contiguous rows; "NT")
//   BNT = false: B is [K,N] row-major ("NN")
// 64x64 tile, Kt=32, 256 threads, 4x4 per-thread microtile.
// ---------------------------------------------------------------------------
template <bool BNT, bool HASBIAS>
__global__ __launch_bounds__(256) void gemm64(
    const float* __restrict__ A, const float* __restrict__ Bm,
    const float* __restrict__ bias, float* __restrict__ C,
    int M, int N, int K)
{
    __shared__ float As[32][65];  // [k][m], +1 pad -> conflict-free scatter stores
    __shared__ float Bs[32][65];  // [k][n]

    const int tid = threadIdx.x;
    const int m0 = blockIdx.y * 64;
    const int n0 = blockIdx.x * 64;
    const int tx = tid & 15;       // 16 col-groups
    const int ty = tid >> 4;       // 16 row-groups

    float acc[4][4];
#pragma unroll
    for (int i = 0; i < 4; i++)
#pragma unroll
        for (int j = 0; j < 4; j++) acc[i][j] = 0.f;

    for (int k0 = 0; k0 < K; k0 += 32) {
        // A tile: 64 rows x 32 k, transposed into As[k][m]
#pragma unroll
        for (int r = 0; r < 2; r++) {
            int idx = tid + r * 256;          // 0..511
            int row = idx >> 3;               // 0..63
            int kc  = (idx & 7) << 2;         // 0,4,...,28
            float4 v = *(const float4*)(A + (size_t)(m0 + row) * K + k0 + kc);
            As[kc + 0][row] = v.x; As[kc + 1][row] = v.y;
            As[kc + 2][row] = v.z; As[kc + 3][row] = v.w;
        }
        if (BNT) {
#pragma unroll
            for (int r = 0; r < 2; r++) {
                int idx = tid + r * 256;
                int row = idx >> 3;           // n index 0..63
                int kc  = (idx & 7) << 2;
                float4 v = *(const float4*)(Bm + (size_t)(n0 + row) * K + k0 + kc);
                Bs[kc + 0][row] = v.x; Bs[kc + 1][row] = v.y;
                Bs[kc + 2][row] = v.z; Bs[kc + 3][row] = v.w;
            }
        } else {
#pragma unroll
            for (int r = 0; r < 2; r++) {
                int idx = tid + r * 256;      // 512 float4 = 32 k-rows x 16 groups
                int kk  = idx >> 4;           // 0..31
                int nc  = (idx & 15) << 2;    // 0..60
                float4 v = *(const float4*)(Bm + (size_t)(k0 + kk) * N + n0 + nc);
                Bs[kk][nc + 0] = v.x; Bs[kk][nc + 1] = v.y;
                Bs[kk][nc + 2] = v.z; Bs[kk][nc + 3] = v.w;
            }
        }
        __syncthreads();

#pragma unroll
        for (int kk = 0; kk < 32; kk++) {
            float a0 = As[kk][ty * 4 + 0], a1 = As[kk][ty * 4 + 1];
            float a2 = As[kk][ty * 4 + 2], a3 = As[kk][ty * 4 + 3];
            float b0 = Bs[kk][tx * 4 + 0], b1 = Bs[kk][tx * 4 + 1];
            float b2 = Bs[kk][tx * 4 + 2], b3 = Bs[kk][tx * 4 + 3];
            acc[0][0] += a0 * b0; acc[0][1] += a0 * b1; acc[0][2] += a0 * b2; acc[0][3] += a0 * b3;
            acc[1][0] += a1 * b0; acc[1][1] += a1 * b1; acc[1][2] += a1 * b2; acc[1][3] += a1 * b3;
            acc[2][0] += a2 * b0; acc[2][1] += a2 * b1; acc[2][2] += a2 * b2; acc[2][3] += a2 * b3;
            acc[3][0] += a3 * b0; acc[3][1] += a3 * b1; acc[3][2] += a3 * b2; acc[3][3] += a3 * b3;
        }
        __syncthreads();
    }

#pragma unroll
    for (int i = 0; i < 4; i++) {
        int row = m0 + ty * 4 + i;
#pragma unroll
        for (int j = 0; j < 4; j++) {
            int col = n0 + tx * 4 + j;
            float v = acc[i][j];
            if (HASBIAS) v += bias[col];
            C[(size_t)row * N + col] = v;
        }
    }
}

// ---------------------------------------------------------------------------
// Streaming online-softmax attention core.
// One CTA per batch row b. Streams past_predictions[b] (256x1024 fp32, 1 MB)
// from DRAM exactly once in ATC-row chunks staged in SMEM.
//   scores[t] = P[b,t,:] . qk[b,:]
//   online softmax across chunks; accumulate ctx_in[b,f] = sum_t w_t P[b,t,f]
// Output: g_ctxin[b,:] (already normalized by the softmax denominator).
// ---------------------------------------------------------------------------
__global__ __launch_bounds__(256) void attn_stream(const float* __restrict__ P)
{
    extern __shared__ float sm[];
    float* Ps  = sm;                       // ATC * Fdim
    float* scs = sm + ATC * Fdim;          // 32  (chunk scores)
    float* wts = scs + 32;                 // 32  (chunk weights)
    float* bc  = wts + 32;                 // [0]=new max, [1]=chunk weight sum

    const int b    = blockIdx.x;
    const int tid  = threadIdx.x;          // 256
    const int lane = tid & 31;
    const int warp = tid >> 5;             // 8 warps

    const float* Pb  = P + (size_t)b * Tdim * Fdim;
    const float* qkb = g_qk + (size_t)b * Fdim;

    // Per-thread cache of the qk elements this lane uses in score dots.
    float qreg[32];
#pragma unroll
    for (int k = 0; k < 32; k++) qreg[k] = qkb[lane + 32 * k];

    const int c0 = tid * 4;                // this thread owns 4 output columns
    float4 acc = make_float4(0.f, 0.f, 0.f, 0.f);
    float m = -1e30f, s = 0.f;

    for (int t0 = 0; t0 < Tdim; t0 += ATC) {
        // Stage chunk: ATC*Fdim floats = ATC*Fdim/4/256 float4 per thread
        const float* src = Pb + (size_t)t0 * Fdim;
#pragma unroll
        for (int r = 0; r < (ATC * Fdim / 4 / 256); r++) {
            int idx = (tid + r * 256) * 4;
            *(float4*)(Ps + idx) = *(const float4*)(src + idx);
        }
        __syncthreads();

        // Scores: warp w handles rows w and w+8
#pragma unroll
        for (int rr = 0; rr < ATC / 8; rr++) {
            int tc = warp + rr * 8;
            const float* row = Ps + tc * Fdim;
            float p = 0.f;
#pragma unroll
            for (int k = 0; k < 32; k++) p += row[lane + 32 * k] * qreg[k];
#pragma unroll
            for (int o = 16; o; o >>= 1) p += __shfl_xor_sync(0xffffffffu, p, o);
            if (lane == 0) scs[tc] = p;
        }
        __syncthreads();

        // Warp 0: chunk max, weights, weight sum
        if (warp == 0) {
            float sc = (lane < ATC) ? scs[lane] : -1e30f;
            float cm = sc;
#pragma unroll
            for (int o = 16; o; o >>= 1) cm = fmaxf(cm, __shfl_xor_sync(0xffffffffu, cm, o));
            float newm = fmaxf(m, cm);
            float w = (lane < ATC) ? __expf(sc - newm) : 0.f;
            if (lane < ATC) wts[lane] = w;
            float sw = w;
#pragma unroll
            for (int o = 16; o; o >>= 1) sw += __shfl_xor_sync(0xffffffffu, sw, o);
            if (lane == 0) { bc[0] = newm; bc[1] = sw; }
        }
        __syncthreads();

        // All threads: rescale running state, accumulate weighted rows
        float newm = bc[0];
        float c = __expf(m - newm);
        s = s * c + bc[1];
        m = newm;
        acc.x *= c; acc.y *= c; acc.z *= c; acc.w *= c;
#pragma unroll
        for (int tc = 0; tc < ATC; tc++) {
            float w = wts[tc];
            float4 v = *(const float4*)(Ps + tc * Fdim + c0);
            acc.x += w * v.x; acc.y += w * v.y;
            acc.z += w * v.z; acc.w += w * v.w;
        }
        __syncthreads();   // protect Ps before next chunk load
    }

    float inv = 1.f / s;
    float4 o = make_float4(acc.x * inv, acc.y * inv, acc.z * inv, acc.w * inv);
    *(float4*)(g_ctxin + (size_t)b * Fdim + c0) = o;
}

// ---------------------------------------------------------------------------
// kernel_launch: query = z@Wq^T + bq ; qk = query@Wk ;
//                ctxin = softmax(P.qk)-weighted sum of P (streaming) ;
//                out = ctxin@Wv^T + bv
// ---------------------------------------------------------------------------
extern "C" void kernel_launch(void* const* d_in, const int* in_sizes, int n_in,
                              void* d_out, int out_size)
{
    const float* z  = (const float*)d_in[0];
    const float* P  = (const float*)d_in[1];
    const float* Wq = (const float*)d_in[2];
    const float* Wk = (const float*)d_in[3];
    const float* Wv = (const float*)d_in[4];
    const float* bq = (const float*)d_in[5];
    const float* bv = (const float*)d_in[7];
    float* out = (float*)d_out;

    float *query, *qk, *ctxin;
    cudaGetSymbolAddress((void**)&query, g_query);
    cudaGetSymbolAddress((void**)&qk,    g_qk);
    cudaGetSymbolAddress((void**)&ctxin, g_ctxin);

    dim3 grid(Fdim / 64, Bdim / 64);   // 16 x 8 = 128 CTAs

    // query = z @ Wq^T + bq   (Wq is [out,in] row-major -> NT)
    gemm64<true, true><<<grid, 256>>>(z, Wq, bq, query, Bdim, Fdim, Fdim);
    // qk = query @ Wk         (Wk is [d,f] row-major, reduce over d -> NN)
    gemm64<false, false><<<grid, 256>>>(query, Wk, nullptr, qk, Bdim, Fdim, Fdim);

    size_t smem = (size_t)(ATC * Fdim + 32 + 32 + 8) * sizeof(float);
    cudaFuncSetAttribute(attn_stream, cudaFuncAttributeMaxDynamicSharedMemorySize, (int)smem);
    attn_stream<<<Bdim, 256, smem>>>(P);

    // out = ctxin @ Wv^T + bv (NT)
    gemm64<true, true><<<grid, 256>>>(ctxin, Wv, bv, out, Bdim, Fdim, Fdim);
}